// round 11
// baseline (speedup 1.0000x reference)
#include <cuda_runtime.h>
#include <math.h>

// J2 plane-strain elastoplasticity PRNN, fused full-sequence kernel, v6.
// 2 material points/thread (packed f32x2); smem-staged x (double buffer);
// register diet for 8 blocks/SM: no ybuf/xs register arrays (scalar STG /
// per-timestep LDS), history stored at stress scale (2MU folded into W1).

namespace {
constexpr double E_MOD_D = 3130.0;
constexpr double NU_D    = 0.37;
constexpr double SIG_Y_D = 64.8;
constexpr double H_ISO_D = 300.0;
constexpr double MU_D    = E_MOD_D / (2.0 * (1.0 + NU_D));
constexpr double LAM_D   = E_MOD_D * NU_D / ((1.0 + NU_D) * (1.0 - 2.0 * NU_D));

constexpr int T_STEPS = 128;
constexpr int F_DIM   = 3;
constexpr int L_DIM   = 48;
constexpr int GROUPS_PER_BLOCK = 16;   // batch elements per block
constexpr int ROW_F = 20;              // padded smem row (floats)
}

// ---- packed f32x2 helpers (sm_103a) ----
typedef unsigned long long f2t;

__device__ __forceinline__ f2t f2pack(float lo, float hi) {
    f2t r;
    asm("mov.b64 %0, {%1, %2};" : "=l"(r) : "f"(lo), "f"(hi));
    return r;
}
__device__ __forceinline__ void f2unpack(f2t a, float& lo, float& hi) {
    asm("mov.b64 {%0, %1}, %2;" : "=f"(lo), "=f"(hi) : "l"(a));
}
__device__ __forceinline__ f2t f2fma(f2t a, f2t b, f2t c) {
    f2t d;
    asm("fma.rn.f32x2 %0, %1, %2, %3;" : "=l"(d) : "l"(a), "l"(b), "l"(c));
    return d;
}
__device__ __forceinline__ f2t f2mul(f2t a, f2t b) {
    f2t d;
    asm("mul.rn.f32x2 %0, %1, %2;" : "=l"(d) : "l"(a), "l"(b));
    return d;
}
__device__ __forceinline__ f2t f2add(f2t a, f2t b) {
    f2t d;
    asm("add.rn.f32x2 %0, %1, %2;" : "=l"(d) : "l"(a), "l"(b));
    return d;
}

__global__ __launch_bounds__(128, 8)
void prnn_j2_kernel6(const float* __restrict__ x,
                     const float* __restrict__ W1,
                     const float* __restrict__ W2,
                     float* __restrict__ out,
                     int n_batch)
{
    const float SIG_Y = (float)SIG_Y_D;
    const float H_ISO = (float)H_ISO_D;
    const float INV_3MU_H = (float)(1.0 / (3.0 * MU_D + H_ISO_D));
    // spk = g * SPK_C * rsqrt(q2), SPK_C = -1.5*2MU/(3MU+H)
    const float SPK_C  = (float)(-3.0 * MU_D / (3.0 * MU_D + H_ISO_D));
    const float TWO_MU = 2.0f * (float)MU_D;
    // pp = (KB/(2MU)) * tr2mu,  KB = LAM + 2MU/3
    const float KB2    = (float)((LAM_D + 2.0 * MU_D / 3.0) / (2.0 * MU_D));

    __shared__ float xs[2][GROUPS_PER_BLOCK][ROW_F];

    const int li  = threadIdx.x;
    const int g   = li >> 3;             // group (batch element) in block
    const int l8  = li & 7;              // lane within 8-lane group
    const int b   = blockIdx.x * GROUPS_PER_BLOCK + g;
    (void)n_batch;

    // loader role: threads 0..47 own one 16B slice of the block slab
    const int  lrow  = li / 3;
    const int  lpart = li % 3;
    const bool isldr = (li < 48);
    const float* lsrc = x + (size_t)(blockIdx.x * GROUPS_PER_BLOCK + lrow) * (T_STEPS * 3)
                          + lpart * 4;

    const int m0 = l8;
    const int m1 = l8 + 8;

    // fc1 rows packed, pre-scaled: rows 0,1 by 2MU, shear row by MU (=2MU*0.5)
    f2t w1p[3][3];
#pragma unroll
    for (int i = 0; i < 3; i++) {
        const float s = (i == 2) ? (float)MU_D : TWO_MU;
#pragma unroll
        for (int j = 0; j < 3; j++)
            w1p[i][j] = f2pack(s * W1[(3 * m0 + i) * F_DIM + j],
                               s * W1[(3 * m1 + i) * F_DIM + j]);
    }

    // softplus(W2) packed
    f2t w2p[3][3];
#pragma unroll
    for (int o = 0; o < 3; o++)
#pragma unroll
        for (int i = 0; i < 3; i++) {
            const float a = W2[o * L_DIM + 3 * m0 + i];
            const float c = W2[o * L_DIM + 3 * m1 + i];
            const float sa = fmaxf(a, 0.0f) + log1pf(expf(-fabsf(a)));
            const float sc = fmaxf(c, 0.0f) + log1pf(expf(-fabsf(c)));
            w2p[o][i] = f2pack(sa, sc);
        }

    const f2t M13p = f2pack(-1.0f / 3.0f, -1.0f / 3.0f);
    const f2t KB2p = f2pack(KB2, KB2);
    const f2t C15p = f2pack(1.5f, 1.5f);
    const f2t ONEp = f2pack(1.0f, 1.0f);
    const f2t ZEROp = f2pack(0.0f, 0.0f);

    // committed history at stress scale: NP = 2MU * (negative plastic strain)
    f2t npxx = ZEROp, npyy = ZEROp, npzz = ZEROp, npxy = ZEROp;
    float alpha0 = 0.0f, alpha1 = 0.0f;

    float* ob = out + (size_t)b * T_STEPS * 3;
    const bool leader = (l8 == 0);

    if (isldr) {
        const float4 v = __ldg(reinterpret_cast<const float4*>(lsrc));
        *reinterpret_cast<float4*>(&xs[0][lrow][lpart * 4]) = v;
    }
    __syncthreads();

    for (int it = 0; it < T_STEPS / 4; ++it) {
        const int t4 = it * 4;
        const int buf = it & 1;

        // prefetch next slab (clamped on last iter)
        float4 pv;
        const int tn = (it < T_STEPS / 4 - 1) ? (t4 + 4) : t4;
        if (isldr)
            pv = __ldg(reinterpret_cast<const float4*>(lsrc + tn * 3));

#pragma unroll
        for (int u = 0; u < 4; u++) {
            // per-timestep strain path from smem (broadcast within group,
            // warp-internal banks conflict-free with ROW_F=20)
            const float xa  = xs[buf][g][3 * u + 0];
            const float xbv = xs[buf][g][3 * u + 1];
            const float xc  = xs[buf][g][3 * u + 2];
            const f2t xp0 = f2pack(xa, xa);
            const f2t xp1 = f2pack(xbv, xbv);
            const f2t xp2 = f2pack(xc, xc);

            // scaled elastic strain: e2 = 2MU*ee  (weights pre-scaled, NP scaled)
            const f2t e2xx = f2fma(w1p[0][0], xp0, f2fma(w1p[0][1], xp1, f2fma(w1p[0][2], xp2, npxx)));
            const f2t e2yy = f2fma(w1p[1][0], xp0, f2fma(w1p[1][1], xp1, f2fma(w1p[1][2], xp2, npyy)));
            const f2t sxy  = f2fma(w1p[2][0], xp0, f2fma(w1p[2][1], xp1, f2fma(w1p[2][2], xp2, npxy)));
            const f2t e2zz = npzz;

            // deviator + mean stress
            const f2t tr2 = f2add(f2add(e2xx, e2yy), e2zz);
            const f2t cc  = f2mul(M13p, tr2);
            const f2t dxx = f2add(e2xx, cc);
            const f2t dyy = f2add(e2yy, cc);
            const f2t dzz = f2add(e2zz, cc);
            const f2t pp  = f2mul(KB2p, tr2);

            // q^2 = 1.5*(dxx^2+dyy^2+dzz^2+2*sxy^2)
            const f2t t2  = f2mul(sxy, sxy);
            const f2t q2p = f2mul(C15p,
                            f2fma(dxx, dxx, f2fma(dyy, dyy, f2fma(dzz, dzz, f2add(t2, t2)))));

            // scalar radial return per half
            float q2a, q2b;
            f2unpack(q2p, q2a, q2b);

            const float rq0 = rsqrtf(fmaxf(q2a, 1e-24f));
            const float rq1 = rsqrtf(fmaxf(q2b, 1e-24f));
            const float qv0 = q2a * rq0;
            const float qv1 = q2b * rq1;
            const float f0 = qv0 - fmaf(H_ISO, alpha0, SIG_Y);
            const float f1 = qv1 - fmaf(H_ISO, alpha1, SIG_Y);
            const float g0 = fmaxf(f0, 0.0f);
            const float g1 = fmaxf(f1, 0.0f);
            alpha0 = fmaf(g0, INV_3MU_H, alpha0);
            alpha1 = fmaf(g1, INV_3MU_H, alpha1);
            const float s0 = (g0 * SPK_C) * rq0;
            const float s1 = (g1 * SPK_C) * rq1;

            const f2t spk = f2pack(s0, s1);       // -3*MU*dgam... = 2MU*cpk
            const f2t w   = f2add(ONEp, spk);     // deviator scale after return

            // corrected stress
            const f2t oxx = f2fma(dxx, w, pp);
            const f2t oyy = f2fma(dyy, w, pp);
            const f2t oxy = f2mul(sxy, w);

            // commit scaled history: NP += spk * d
            npxx = f2fma(spk, dxx, npxx);
            npyy = f2fma(spk, dyy, npyy);
            npzz = f2fma(spk, dzz, npzz);
            npxy = f2fma(spk, sxy, npxy);

            // fc2 partials, pair-sum + 8-lane butterfly
            const f2t y0p = f2fma(w2p[0][0], oxx, f2fma(w2p[0][1], oyy, f2mul(w2p[0][2], oxy)));
            const f2t y1p = f2fma(w2p[1][0], oxx, f2fma(w2p[1][1], oyy, f2mul(w2p[1][2], oxy)));
            const f2t y2p = f2fma(w2p[2][0], oxx, f2fma(w2p[2][1], oyy, f2mul(w2p[2][2], oxy)));

            float y0l, y0h, y1l, y1h, y2l, y2h;
            f2unpack(y0p, y0l, y0h);
            f2unpack(y1p, y1l, y1h);
            f2unpack(y2p, y2l, y2h);
            float y0 = y0l + y0h;
            float y1 = y1l + y1h;
            float y2 = y2l + y2h;

#pragma unroll
            for (int off = 4; off >= 1; off >>= 1) {
                y0 += __shfl_xor_sync(0xffffffffu, y0, off);
                y1 += __shfl_xor_sync(0xffffffffu, y1, off);
                y2 += __shfl_xor_sync(0xffffffffu, y2, off);
            }
            if (leader) {
                ob[(t4 + u) * 3 + 0] = y0;
                ob[(t4 + u) * 3 + 1] = y1;
                ob[(t4 + u) * 3 + 2] = y2;
            }
        }

        if (isldr)
            *reinterpret_cast<float4*>(&xs[buf ^ 1][lrow][lpart * 4]) = pv;
        __syncthreads();
    }
}

extern "C" void kernel_launch(void* const* d_in, const int* in_sizes, int n_in,
                              void* d_out, int out_size)
{
    const float* x  = (const float*)d_in[0];   // [B, 128, 3]
    const float* W1 = (const float*)d_in[1];   // [48, 3]
    const float* W2 = (const float*)d_in[2];   // [3, 48]
    float* out = (float*)d_out;                // [B, 128, 3]

    const int n_batch = in_sizes[0] / (T_STEPS * F_DIM);   // 16384
    const int blocks = n_batch / GROUPS_PER_BLOCK;          // 1024
    prnn_j2_kernel6<<<blocks, 128>>>(x, W1, W2, out, n_batch);
}